// round 2
// baseline (speedup 1.0000x reference)
#include <cuda_runtime.h>
#include <cuda_fp16.h>
#include <cstdint>
#include <cstddef>

// Problem constants
constexpr int Bb = 64;
constexpr int Ss = 2048;
constexpr int Hh = 1024;
constexpr int Kk = 2048;        // 2H (reduction dim of big GEMM)
constexpr int BS = Bb * Ss;     // 131072 rows
constexpr int MT = 128;         // CTA M tile
constexpr int NT = 128;         // CTA N tile
constexpr int KT = 32;          // K chunk per smem stage
constexpr int NTILES_N = Hh / NT;   // 8
constexpr int ASTRIDE = KT + 8;     // 40 halves (80B rows: conflict-free ldmatrix)
constexpr int BSTRIDE = NT + 8;     // 136 halves (272B rows: conflict-free ldmatrix)

// Scratch (allocation-free contract: __device__ globals)
__device__ float g_decf[Bb * Hh];          // dec_f: [B, H]   (256 KB)
__device__ float g_pe[NTILES_N * BS];      // partial energies per N-tile (4 MB)

// ---------------------------------------------------------------------------
// Kernel 0: dec_f[b,k] = sum_h dh[b,h] * Wh[h,k]
// ---------------------------------------------------------------------------
__global__ void decf_kernel(const float* __restrict__ dh,
                            const float* __restrict__ Wh) {
    __shared__ float dh_s[Hh];
    const int b = blockIdx.y;
    const int k = blockIdx.x * 128 + threadIdx.x;
    for (int h = threadIdx.x; h < Hh; h += 128) dh_s[h] = dh[b * Hh + h];
    __syncthreads();
    float acc = 0.f;
#pragma unroll 8
    for (int h = 0; h < Hh; ++h) acc += dh_s[h] * Wh[h * Hh + k];
    g_decf[b * Hh + k] = acc;
}

// ---------------------------------------------------------------------------
// Kernel 1: fused energy GEMM.
//   For an M-tile (128 flattened (b,s) rows) x N-tile (128 of H cols):
//     acc = E_tile(fp16) @ Ws_tile(fp16)   [K = 2048, fp32 accum]
//     partial_energy[row] = sum_n tanh(acc + dec_f[b,n]) * v[n]
//   written to g_pe[n_tile][row]; softmax kernel sums the 8 partials.
// ---------------------------------------------------------------------------
__global__ __launch_bounds__(256, 2)
void energy_kernel(const float* __restrict__ E,
                   const float* __restrict__ Ws,
                   const float* __restrict__ v) {
    __shared__ __half As[MT][ASTRIDE];     // E tile, row-major [m][k]
    __shared__ __half Bs[KT][BSTRIDE];     // Ws tile, k-major  [k][n]
    __shared__ float t_s[NT];
    __shared__ float v_s[NT];
    __shared__ float pe_s[4][MT];

    const int tid  = threadIdx.x;
    const int lane = tid & 31;
    const int wid  = tid >> 5;
    const int wm   = wid >> 2;   // 0..1  (warp row: 64 M-rows)
    const int wn   = wid & 3;    // 0..3  (warp col: 32 N-cols)
    const int g    = lane >> 2;  // 0..7
    const int tq   = lane & 3;   // 0..3

    const int n0 = blockIdx.x * NT;
    const int m0 = blockIdx.y * MT;
    const int batch = m0 / Ss;   // all 128 rows of a tile share b (S % MT == 0)

    if (tid < NT) {
        t_s[tid] = g_decf[batch * Hh + n0 + tid];
        v_s[tid] = v[n0 + tid];
    }

    float acc[4][4][4];
#pragma unroll
    for (int i = 0; i < 4; i++)
#pragma unroll
        for (int j = 0; j < 4; j++)
#pragma unroll
            for (int q = 0; q < 4; q++) acc[i][j][q] = 0.f;

    // global->smem mapping (256 threads, 4 passes each for A and B)
    const int ar = tid >> 3;          // A row 0..31 (+32/pass)
    const int ak = (tid & 7) * 4;     // A k offset
    const int bk = tid >> 5;          // B k row 0..7 (+8/pass)
    const int bn = lane * 4;          // B n offset 0..124

    for (int kc = 0; kc < Kk; kc += KT) {
        __syncthreads();   // previous compute done before overwrite
#pragma unroll
        for (int p = 0; p < 4; ++p) {
            int r = p * 32 + ar;
            float4 f = *reinterpret_cast<const float4*>(
                &E[(size_t)(m0 + r) * Kk + kc + ak]);
            __half2* dst = reinterpret_cast<__half2*>(&As[r][ak]);
            dst[0] = __floats2half2_rn(f.x, f.y);
            dst[1] = __floats2half2_rn(f.z, f.w);
        }
#pragma unroll
        for (int p = 0; p < 4; ++p) {
            int k = p * 8 + bk;
            float4 f = *reinterpret_cast<const float4*>(
                &Ws[(size_t)(kc + k) * Hh + n0 + bn]);
            __half2* dst = reinterpret_cast<__half2*>(&Bs[k][bn]);
            dst[0] = __floats2half2_rn(f.x, f.y);
            dst[1] = __floats2half2_rn(f.z, f.w);
        }
        __syncthreads();

#pragma unroll
        for (int ks = 0; ks < 2; ++ks) {
            const int k0 = ks * 16;
            uint32_t a[4][4];
            uint32_t bb[4][2];
#pragma unroll
            for (int mi = 0; mi < 4; ++mi) {
                uint32_t addr = (uint32_t)__cvta_generic_to_shared(
                    &As[wm * 64 + mi * 16 + (lane & 15)][k0 + (lane >> 4) * 8]);
                asm volatile(
                    "ldmatrix.sync.aligned.m8n8.x4.shared.b16 {%0,%1,%2,%3}, [%4];\n"
                    : "=r"(a[mi][0]), "=r"(a[mi][1]), "=r"(a[mi][2]), "=r"(a[mi][3])
                    : "r"(addr) : "memory");
            }
#pragma unroll
            for (int ni = 0; ni < 4; ++ni) {
                uint32_t addr = (uint32_t)__cvta_generic_to_shared(
                    &Bs[k0 + (lane & 15)][wn * 32 + ni * 8]);
                asm volatile(
                    "ldmatrix.sync.aligned.m8n8.x2.trans.shared.b16 {%0,%1}, [%2];\n"
                    : "=r"(bb[ni][0]), "=r"(bb[ni][1])
                    : "r"(addr) : "memory");
            }
#pragma unroll
            for (int mi = 0; mi < 4; ++mi)
#pragma unroll
                for (int ni = 0; ni < 4; ++ni) {
                    asm volatile(
                        "mma.sync.aligned.m16n8k16.row.col.f32.f16.f16.f32 "
                        "{%0,%1,%2,%3}, {%4,%5,%6,%7}, {%8,%9}, {%0,%1,%2,%3};\n"
                        : "+f"(acc[mi][ni][0]), "+f"(acc[mi][ni][1]),
                          "+f"(acc[mi][ni][2]), "+f"(acc[mi][ni][3])
                        : "r"(a[mi][0]), "r"(a[mi][1]), "r"(a[mi][2]), "r"(a[mi][3]),
                          "r"(bb[ni][0]), "r"(bb[ni][1]));
                }
        }
    }

    // Epilogue: tanh(acc + dec_f) * v, reduced over the 128 N-cols of the tile.
    float pr[4][2];
#pragma unroll
    for (int mi = 0; mi < 4; ++mi) { pr[mi][0] = 0.f; pr[mi][1] = 0.f; }
#pragma unroll
    for (int mi = 0; mi < 4; ++mi)
#pragma unroll
        for (int ni = 0; ni < 4; ++ni) {
            const int col = wn * 32 + ni * 8 + tq * 2;
            const float t0 = t_s[col], t1 = t_s[col + 1];
            const float v0 = v_s[col], v1 = v_s[col + 1];
            pr[mi][0] += tanhf(acc[mi][ni][0] + t0) * v0
                       + tanhf(acc[mi][ni][1] + t1) * v1;
            pr[mi][1] += tanhf(acc[mi][ni][2] + t0) * v0
                       + tanhf(acc[mi][ni][3] + t1) * v1;
        }
#pragma unroll
    for (int mi = 0; mi < 4; ++mi)
#pragma unroll
        for (int hh = 0; hh < 2; ++hh) {
            float x = pr[mi][hh];
            x += __shfl_xor_sync(0xffffffffu, x, 1);
            x += __shfl_xor_sync(0xffffffffu, x, 2);
            pr[mi][hh] = x;
        }
    if (tq == 0) {
#pragma unroll
        for (int mi = 0; mi < 4; ++mi) {
            const int row = wm * 64 + mi * 16 + g;
            pe_s[wn][row]     = pr[mi][0];
            pe_s[wn][row + 8] = pr[mi][1];
        }
    }
    __syncthreads();
    if (tid < MT) {
        float s = pe_s[0][tid] + pe_s[1][tid] + pe_s[2][tid] + pe_s[3][tid];
        g_pe[(size_t)blockIdx.x * BS + m0 + tid] = s;
    }
}

// ---------------------------------------------------------------------------
// Kernel 2: sum partials, mask, softmax over S per batch row.
// ---------------------------------------------------------------------------
__global__ void softmax_kernel(const int* __restrict__ mask,
                               float* __restrict__ attn) {
    __shared__ float e_s[Ss];
    __shared__ float red[256];
    const int b = blockIdx.x;
    const int tid = threadIdx.x;
    const size_t r0 = (size_t)b * Ss;

    for (int s = tid; s < Ss; s += 256) {
        const size_t r = r0 + s;
        float e = 0.f;
#pragma unroll
        for (int c = 0; c < NTILES_N; ++c) e += g_pe[(size_t)c * BS + r];
        if (mask[r] == 0) e = -1e10f;
        e_s[s] = e;
    }
    __syncthreads();

    float m = -INFINITY;
    for (int s = tid; s < Ss; s += 256) m = fmaxf(m, e_s[s]);
    red[tid] = m;
    __syncthreads();
    for (int o = 128; o > 0; o >>= 1) {
        if (tid < o) red[tid] = fmaxf(red[tid], red[tid + o]);
        __syncthreads();
    }
    const float rowmax = red[0];
    __syncthreads();

    float lsum = 0.f;
    for (int s = tid; s < Ss; s += 256) {
        const float ex = expf(e_s[s] - rowmax);
        e_s[s] = ex;
        lsum += ex;
    }
    red[tid] = lsum;
    __syncthreads();
    for (int o = 128; o > 0; o >>= 1) {
        if (tid < o) red[tid] += red[tid + o];
        __syncthreads();
    }
    const float inv = 1.0f / red[0];
    for (int s = tid; s < Ss; s += 256) attn[r0 + s] = e_s[s] * inv;
}

// ---------------------------------------------------------------------------
// Kernel 3: context[b,e] = sum_s attn[b,s] * E[b,s,e]  (memory-bound GEMV)
// ---------------------------------------------------------------------------
__global__ void context_kernel(const float* __restrict__ E,
                               const float* __restrict__ attn,
                               float* __restrict__ ctx) {
    __shared__ float w_s[Ss];
    const int b = blockIdx.y;
    const int e = blockIdx.x * 256 + threadIdx.x;
    for (int s = threadIdx.x; s < Ss; s += 256) w_s[s] = attn[(size_t)b * Ss + s];
    __syncthreads();
    const float* Eb = E + (size_t)b * Ss * Kk;
    float a0 = 0.f, a1 = 0.f, a2 = 0.f, a3 = 0.f;
    for (int s = 0; s < Ss; s += 4) {
        a0 += w_s[s]     * Eb[(size_t)s * Kk + e];
        a1 += w_s[s + 1] * Eb[(size_t)(s + 1) * Kk + e];
        a2 += w_s[s + 2] * Eb[(size_t)(s + 2) * Kk + e];
        a3 += w_s[s + 3] * Eb[(size_t)(s + 3) * Kk + e];
    }
    ctx[(size_t)b * Kk + e] = (a0 + a1) + (a2 + a3);
}

// ---------------------------------------------------------------------------
extern "C" void kernel_launch(void* const* d_in, const int* in_sizes, int n_in,
                              void* d_out, int out_size) {
    const float* dh   = (const float*)d_in[0];   // decoder_hidden [B,H]
    const float* E    = (const float*)d_in[1];   // encoder_outputs [B,S,2H]
    const int*   mask = (const int*)d_in[2];     // src_mask [B,S]
    const float* Wh   = (const float*)d_in[3];   // [H,H]
    const float* Ws   = (const float*)d_in[4];   // [2H,H]
    const float* v    = (const float*)d_in[5];   // [H]

    float* out  = (float*)d_out;
    float* ctx  = out;                           // context [B,2H]
    float* attn = out + (size_t)Bb * Kk;         // attn    [B,S]

    decf_kernel<<<dim3(Hh / 128, Bb), 128>>>(dh, Wh);
    energy_kernel<<<dim3(NTILES_N, BS / MT), 256>>>(E, Ws, v);
    softmax_kernel<<<Bb, 256>>>(mask, attn);
    context_kernel<<<dim3(Kk / 256, Bb), 256>>>(E, attn, ctx);
}

// round 6
// speedup vs baseline: 1.1749x; 1.1749x over previous
#include <cuda_runtime.h>
#include <cuda_fp16.h>
#include <cstdint>
#include <cstddef>

// ---------------------------------------------------------------------------
// Problem constants
// ---------------------------------------------------------------------------
constexpr int Bb = 64;
constexpr int Ss = 2048;
constexpr int Hh = 1024;
constexpr int Kk = 2048;          // 2H reduction dim
constexpr int BS = Bb * Ss;       // 131072 rows
constexpr int MT = 128;           // CTA M tile
constexpr int NT = 256;           // CTA N tile
constexpr int NTILES = Hh / NT;   // 4
constexpr int KCH = 32;           // K chunk (halves)
constexpr int NCH = Kk / KCH;     // 64 chunks
constexpr int STAGES = 4;

// Padded smem strides (halves) — conflict-free for ldmatrix
constexpr int ASTR = KCH + 8;     // 40 halves = 80B rows
constexpr int BSTR = NT + 8;      // 264 halves = 528B rows
constexpr int ABYTES = MT * ASTR * 2;    // 10240 per stage
constexpr int BBYTES = KCH * BSTR * 2;   // 16896 per stage

// Dynamic smem layout (bytes)
constexpr int OFF_A = 0;
constexpr int OFF_B = OFF_A + STAGES * ABYTES;      // 40960
constexpr int OFF_T = OFF_B + STAGES * BBYTES;      // 108544
constexpr int OFF_V = OFF_T + NT * 4;
constexpr int OFF_PE = OFF_V + NT * 4;
constexpr int SM_TOTAL = OFF_PE + 4 * MT * 4;       // 112640

// Scratch (__device__ globals: allocation-free contract)
__device__ float  g_decf[Bb * Hh];
__device__ float  g_pe[NTILES * BS];
__device__ __half g_Wsh[(size_t)Kk * Hh];          // Ws in fp16, [K][H]
__device__ __half g_Eh[(size_t)BS * Kk];           // E in fp16,  [BS][2H] (512MB)

__device__ __forceinline__ float fast_tanh(float x) {
    float y; asm("tanh.approx.f32 %0, %1;" : "=f"(y) : "f"(x)); return y;
}

// ---------------------------------------------------------------------------
// Kernel 0: dec_f = dh @ Wh
// ---------------------------------------------------------------------------
__global__ void decf_kernel(const float* __restrict__ dh,
                            const float* __restrict__ Wh) {
    __shared__ float dh_s[Hh];
    const int b = blockIdx.y;
    const int k = blockIdx.x * 128 + threadIdx.x;
    for (int h = threadIdx.x; h < Hh; h += 128) dh_s[h] = dh[b * Hh + h];
    __syncthreads();
    float acc = 0.f;
#pragma unroll 8
    for (int h = 0; h < Hh; ++h) acc += dh_s[h] * Wh[h * Hh + k];
    g_decf[b * Hh + k] = acc;
}

// ---------------------------------------------------------------------------
// Kernel 0b/0c: fp32 -> fp16 elementwise converts (memory-bound)
// ---------------------------------------------------------------------------
__global__ void cvt_ws_kernel(const float* __restrict__ Ws) {
    const size_t i4 = (size_t)blockIdx.x * 256 + threadIdx.x;   // covers 4 elems
    float4 f = reinterpret_cast<const float4*>(Ws)[i4];
    __half2 h0 = __floats2half2_rn(f.x, f.y);
    __half2 h1 = __floats2half2_rn(f.z, f.w);
    uint2 u; u.x = *(uint32_t*)&h0; u.y = *(uint32_t*)&h1;
    reinterpret_cast<uint2*>(g_Wsh)[i4] = u;
}
__global__ void cvt_e_kernel(const float* __restrict__ E) {
    const size_t i4 = (size_t)blockIdx.x * 256 + threadIdx.x;
    float4 f = reinterpret_cast<const float4*>(E)[i4];
    __half2 h0 = __floats2half2_rn(f.x, f.y);
    __half2 h1 = __floats2half2_rn(f.z, f.w);
    uint2 u; u.x = *(uint32_t*)&h0; u.y = *(uint32_t*)&h1;
    reinterpret_cast<uint2*>(g_Eh)[i4] = u;
}

// ---------------------------------------------------------------------------
// Kernel 1: fused energy GEMM (mma.sync, 4-stage cp.async pipeline).
//   acc[128,256] = Eh_tile @ Wsh_tile (K=2048, fp32 acc)
//   partial_energy[row] = sum_n tanh(acc + dec_f) * v   -> g_pe[ntile]
// ---------------------------------------------------------------------------
__global__ __launch_bounds__(256, 1)
void energy_kernel(const float* __restrict__ v) {
    extern __shared__ char sm[];
    const uint32_t sb = (uint32_t)__cvta_generic_to_shared(sm);
    const int tid = threadIdx.x, wid = tid >> 5, lane = tid & 31;
    const int wm = wid >> 2, wn = wid & 3;       // warp tile (64 x 64) grid 2x4
    const int g = lane >> 2, tq = lane & 3;
    const int nt = blockIdx.x;                   // 0..3 (fastest: L2 reuse of A)
    const int m0 = blockIdx.y * MT;
    const int n0 = nt * NT;
    const int batch = m0 >> 11;                  // m0 / Ss

    float* t_s = (float*)(sm + OFF_T);
    float* v_s = (float*)(sm + OFF_V);
    t_s[tid] = g_decf[batch * Hh + n0 + tid];
    v_s[tid] = v[n0 + tid];

    float acc[4][8][4];
#pragma unroll
    for (int i = 0; i < 4; ++i)
#pragma unroll
        for (int j = 0; j < 8; ++j)
#pragma unroll
            for (int q = 0; q < 4; ++q) acc[i][j][q] = 0.f;

    auto load_stage = [&](int st, int kc) {
        const uint32_t ab = sb + OFF_A + st * ABYTES;
#pragma unroll
        for (int i = 0; i < 2; ++i) {            // A: 512 x 16B chunks
            const int c = tid + i * 256;
            const int row = c >> 2, o = c & 3;
            const uint32_t dst = ab + row * 80 + o * 16;
            const __half* src = &g_Eh[(size_t)(m0 + row) * Kk + kc + o * 8];
            asm volatile("cp.async.cg.shared.global [%0], [%1], 16;"
                         :: "r"(dst), "l"(src) : "memory");
        }
        const uint32_t bb = sb + OFF_B + st * BBYTES;
#pragma unroll
        for (int i = 0; i < 4; ++i) {            // B: 1024 x 16B chunks
            const int c = tid + i * 256;
            const int kr = c >> 5, o = c & 31;
            const uint32_t dst = bb + kr * 528 + o * 16;
            const __half* src = &g_Wsh[(size_t)(kc + kr) * Hh + n0 + o * 8];
            asm volatile("cp.async.cg.shared.global [%0], [%1], 16;"
                         :: "r"(dst), "l"(src) : "memory");
        }
        asm volatile("cp.async.commit_group;" ::: "memory");
    };

#pragma unroll
    for (int s = 0; s < STAGES - 1; ++s) load_stage(s, s * KCH);

    for (int c = 0; c < NCH; ++c) {
        const int st = c & (STAGES - 1);
        asm volatile("cp.async.wait_group 2;" ::: "memory");
        __syncthreads();

        const uint32_t ab = sb + OFF_A + st * ABYTES;
        const uint32_t bb = sb + OFF_B + st * BBYTES;
#pragma unroll
        for (int ks = 0; ks < 2; ++ks) {
            const int k0 = ks * 16;
            uint32_t a[4][4], b[8][2];
#pragma unroll
            for (int mi = 0; mi < 4; ++mi) {
                const uint32_t addr = ab + (wm * 64 + mi * 16 + (lane & 15)) * 80
                                    + (k0 + (lane >> 4) * 8) * 2;
                asm volatile(
                    "ldmatrix.sync.aligned.m8n8.x4.shared.b16 {%0,%1,%2,%3}, [%4];"
                    : "=r"(a[mi][0]), "=r"(a[mi][1]), "=r"(a[mi][2]), "=r"(a[mi][3])
                    : "r"(addr));
            }
#pragma unroll
            for (int ni = 0; ni < 8; ++ni) {
                const uint32_t addr = bb + (k0 + (lane & 15)) * 528
                                    + (wn * 64 + ni * 8) * 2;
                asm volatile(
                    "ldmatrix.sync.aligned.m8n8.x2.trans.shared.b16 {%0,%1}, [%2];"
                    : "=r"(b[ni][0]), "=r"(b[ni][1]) : "r"(addr));
            }
#pragma unroll
            for (int mi = 0; mi < 4; ++mi)
#pragma unroll
                for (int ni = 0; ni < 8; ++ni) {
                    asm volatile(
                        "mma.sync.aligned.m16n8k16.row.col.f32.f16.f16.f32 "
                        "{%0,%1,%2,%3}, {%4,%5,%6,%7}, {%8,%9}, {%0,%1,%2,%3};"
                        : "+f"(acc[mi][ni][0]), "+f"(acc[mi][ni][1]),
                          "+f"(acc[mi][ni][2]), "+f"(acc[mi][ni][3])
                        : "r"(a[mi][0]), "r"(a[mi][1]), "r"(a[mi][2]), "r"(a[mi][3]),
                          "r"(b[ni][0]), "r"(b[ni][1]));
                }
        }
        if (c + STAGES - 1 < NCH) load_stage((c + STAGES - 1) & (STAGES - 1),
                                             (c + STAGES - 1) * KCH);
    }

    // Epilogue: tanh(acc + dec_f) * v, reduce over this tile's 256 N cols.
    float pr[4][2];
#pragma unroll
    for (int mi = 0; mi < 4; ++mi) { pr[mi][0] = 0.f; pr[mi][1] = 0.f; }
#pragma unroll
    for (int mi = 0; mi < 4; ++mi)
#pragma unroll
        for (int ni = 0; ni < 8; ++ni) {
            const int col = wn * 64 + ni * 8 + tq * 2;
            const float t0 = t_s[col], t1 = t_s[col + 1];
            const float v0 = v_s[col], v1 = v_s[col + 1];
            pr[mi][0] += fast_tanh(acc[mi][ni][0] + t0) * v0
                       + fast_tanh(acc[mi][ni][1] + t1) * v1;
            pr[mi][1] += fast_tanh(acc[mi][ni][2] + t0) * v0
                       + fast_tanh(acc[mi][ni][3] + t1) * v1;
        }
#pragma unroll
    for (int mi = 0; mi < 4; ++mi)
#pragma unroll
        for (int hh = 0; hh < 2; ++hh) {
            float x = pr[mi][hh];
            x += __shfl_xor_sync(0xffffffffu, x, 1);
            x += __shfl_xor_sync(0xffffffffu, x, 2);
            pr[mi][hh] = x;
        }
    float* pe = (float*)(sm + OFF_PE);           // [4 wn][128 rows]
    __syncthreads();
    if (tq == 0) {
#pragma unroll
        for (int mi = 0; mi < 4; ++mi) {
            const int row = wm * 64 + mi * 16 + g;
            pe[wn * MT + row]     = pr[mi][0];
            pe[wn * MT + row + 8] = pr[mi][1];
        }
    }
    __syncthreads();
    if (tid < MT)
        g_pe[(size_t)nt * BS + m0 + tid] =
            pe[tid] + pe[MT + tid] + pe[2 * MT + tid] + pe[3 * MT + tid];
}

// ---------------------------------------------------------------------------
// Kernel 2: sum partials, mask, softmax over S per batch row.
// ---------------------------------------------------------------------------
__global__ void softmax_kernel(const int* __restrict__ mask,
                               float* __restrict__ attn) {
    __shared__ float e_s[Ss];
    __shared__ float red[256];
    const int b = blockIdx.x, tid = threadIdx.x;
    const size_t r0 = (size_t)b * Ss;
    for (int s = tid; s < Ss; s += 256) {
        const size_t r = r0 + s;
        float e = 0.f;
#pragma unroll
        for (int c = 0; c < NTILES; ++c) e += g_pe[(size_t)c * BS + r];
        if (mask[r] == 0) e = -1e10f;
        e_s[s] = e;
    }
    __syncthreads();
    float m = -INFINITY;
    for (int s = tid; s < Ss; s += 256) m = fmaxf(m, e_s[s]);
    red[tid] = m; __syncthreads();
    for (int o = 128; o > 0; o >>= 1) {
        if (tid < o) red[tid] = fmaxf(red[tid], red[tid + o]);
        __syncthreads();
    }
    const float rowmax = red[0]; __syncthreads();
    float lsum = 0.f;
    for (int s = tid; s < Ss; s += 256) {
        const float ex = expf(e_s[s] - rowmax);
        e_s[s] = ex; lsum += ex;
    }
    red[tid] = lsum; __syncthreads();
    for (int o = 128; o > 0; o >>= 1) {
        if (tid < o) red[tid] += red[tid + o];
        __syncthreads();
    }
    const float inv = 1.0f / red[0];
    for (int s = tid; s < Ss; s += 256) attn[r0 + s] = e_s[s] * inv;
}

// ---------------------------------------------------------------------------
// Kernel 3: context[b,e] = sum_s attn[b,s] * Eh[b,s,e]  (fp16 E copy; HBM-bound)
// ---------------------------------------------------------------------------
__global__ void context_kernel(const float* __restrict__ attn,
                               float* __restrict__ ctx) {
    __shared__ float w_s[Ss];
    const int b = blockIdx.y;
    const int e = (blockIdx.x * 256 + threadIdx.x) * 2;
    for (int s = threadIdx.x; s < Ss; s += 256) w_s[s] = attn[(size_t)b * Ss + s];
    __syncthreads();
    const __half* Eb = g_Eh + (size_t)b * Ss * Kk;
    float ax = 0.f, ay = 0.f, bx = 0.f, by = 0.f;
    for (int s = 0; s < Ss; s += 2) {
        const float w0 = w_s[s], w1 = w_s[s + 1];
        float2 f0 = __half22float2(*reinterpret_cast<const __half2*>(
            &Eb[(size_t)s * Kk + e]));
        float2 f1 = __half22float2(*reinterpret_cast<const __half2*>(
            &Eb[(size_t)(s + 1) * Kk + e]));
        ax += w0 * f0.x; ay += w0 * f0.y;
        bx += w1 * f1.x; by += w1 * f1.y;
    }
    ctx[(size_t)b * Kk + e]     = ax + bx;
    ctx[(size_t)b * Kk + e + 1] = ay + by;
}

// ---------------------------------------------------------------------------
extern "C" void kernel_launch(void* const* d_in, const int* in_sizes, int n_in,
                              void* d_out, int out_size) {
    const float* dh   = (const float*)d_in[0];
    const float* E    = (const float*)d_in[1];
    const int*   mask = (const int*)d_in[2];
    const float* Wh   = (const float*)d_in[3];
    const float* Ws   = (const float*)d_in[4];
    const float* v    = (const float*)d_in[5];

    float* out  = (float*)d_out;
    float* ctx  = out;                        // [B, 2H]
    float* attn = out + (size_t)Bb * Kk;      // [B, S]

    // Idempotent, non-stream host call: safe under graph capture, no static guard.
    cudaFuncSetAttribute(energy_kernel,
                         cudaFuncAttributeMaxDynamicSharedMemorySize, SM_TOTAL);

    decf_kernel<<<dim3(Hh / 128, Bb), 128>>>(dh, Wh);
    cvt_ws_kernel<<<(Kk * Hh / 4) / 256, 256>>>(Ws);
    cvt_e_kernel<<<(int)(((size_t)BS * Kk / 4) / 256), 256>>>(E);
    energy_kernel<<<dim3(NTILES, BS / MT), 256, SM_TOTAL>>>(v);
    softmax_kernel<<<Bb, 256>>>(mask, attn);
    context_kernel<<<dim3(Kk / 512, Bb), 256>>>(attn, ctx);
}